// round 1
// baseline (speedup 1.0000x reference)
#include <cuda_runtime.h>
#include <cstdint>

#define F_DIM   16
#define E_DIM   128
#define H_DIM   128
#define IN_DIM  144      // F + E
#define TILE_M  128
#define THREADS 256
#define A_PITCH 148      // 144 + 4 pad, keeps float4 alignment

typedef unsigned long long u64;

// scratch (device globals: no allocations allowed)
__device__ int g_seg_arr[2000256];
__device__ int g_ptr32[33024];

// ---------------- packed f32x2 helpers (FFMA2 path) ----------------
__device__ __forceinline__ u64 pack_dup(float a) {
    u64 r;
    asm("mov.b64 %0, {%1, %1};" : "=l"(r) : "f"(a));
    return r;
}
__device__ __forceinline__ u64 pack2(float a, float b) {
    u64 r;
    asm("mov.b64 %0, {%1, %2};" : "=l"(r) : "f"(a), "f"(b));
    return r;
}
__device__ __forceinline__ void fma2(u64 &acc, u64 a, u64 b) {
    asm("fma.rn.f32x2 %0, %1, %2, %0;" : "+l"(acc) : "l"(a), "l"(b));
}
__device__ __forceinline__ float2 unpack2(u64 v) {
    float2 r;
    asm("mov.b64 {%0, %1}, %2;" : "=f"(r.x), "=f"(r.y) : "l"(v));
    return r;
}

// ---------------- prep: zero output + normalize ptr to int32 ----------------
__global__ void prep_kernel(const void* __restrict__ ptr_raw, float* __restrict__ out,
                            int out_elems, int Bseg, int N) {
    int idx = blockIdx.x * blockDim.x + threadIdx.x;
    if (idx < out_elems) out[idx] = 0.0f;
    if (idx <= Bseg) {
        const int* p32 = (const int*)ptr_raw;
        // If ptr is int32, p32[Bseg] is the last element == N.
        // If ptr is int64, p32[Bseg] is the low word of element Bseg/2, strictly < N.
        bool is64 = (p32[Bseg] != N);
        int v = is64 ? (int)(((const long long*)ptr_raw)[idx]) : p32[idx];
        g_ptr32[idx] = v;
    }
}

// ---------------- seg ids: node i -> segment (searchsorted right - 1) ----------------
__global__ void seg_kernel(int N, int Bseg) {
    int i = blockIdx.x * blockDim.x + threadIdx.x;
    if (i >= N) return;
    int lo = 0, hi = Bseg + 1;
    while (lo < hi) {
        int mid = (lo + hi) >> 1;
        if (g_ptr32[mid] <= i) lo = mid + 1; else hi = mid;
    }
    g_seg_arr[i] = lo - 1;
}

// ---------------- 8x8 micro-tile GEMM over shared memory ----------------
template<int KDIM>
__device__ __forceinline__ void gemm_k(const float* __restrict__ AH,
                                       const float* __restrict__ Ws,
                                       const int rows[8], int c0, u64 acc[8][4]) {
    #pragma unroll 1
    for (int k0 = 0; k0 < KDIM; k0 += 4) {
        float4 av[8];
        #pragma unroll
        for (int i = 0; i < 8; ++i)
            av[i] = *(const float4*)&AH[rows[i] * A_PITCH + k0];
        #pragma unroll
        for (int kk = 0; kk < 4; ++kk) {
            const float* wrow = Ws + (k0 + kk) * H_DIM + c0;
            float4 w0 = *(const float4*)wrow;
            float4 w1 = *(const float4*)(wrow + 4);
            u64 bp0 = pack2(w0.x, w0.y);
            u64 bp1 = pack2(w0.z, w0.w);
            u64 bp2 = pack2(w1.x, w1.y);
            u64 bp3 = pack2(w1.z, w1.w);
            #pragma unroll
            for (int i = 0; i < 8; ++i) {
                float a = (kk == 0) ? av[i].x : (kk == 1) ? av[i].y
                        : (kk == 2) ? av[i].z : av[i].w;
                u64 ap = pack_dup(a);
                fma2(acc[i][0], ap, bp0);
                fma2(acc[i][1], ap, bp1);
                fma2(acc[i][2], ap, bp2);
                fma2(acc[i][3], ap, bp3);
            }
        }
    }
}

// ---------------- fused MLP + segment-sum, persistent grid ----------------
__global__ __launch_bounds__(THREADS, 1)
void fused_kernel(const float* __restrict__ x, const float* __restrict__ hn,
                  const float* __restrict__ W1g, const float* __restrict__ b1g,
                  const float* __restrict__ W2g, const float* __restrict__ b2g,
                  float* __restrict__ out, int N, int numTiles) {
    extern __shared__ float sm[];
    float* W1s = sm;                         // [144][128]
    float* W2s = W1s + IN_DIM * H_DIM;       // [128][128]
    float* b1s = W2s + H_DIM * E_DIM;        // [128]
    float* b2s = b1s + H_DIM;                // [128]
    float* AH  = b2s + E_DIM;                // [128][A_PITCH], doubles as A then H1

    const int tid = threadIdx.x;

    // One-time weight load into smem
    {
        const float4* s1 = (const float4*)W1g; float4* d1 = (float4*)W1s;
        for (int i = tid; i < IN_DIM * H_DIM / 4; i += THREADS) d1[i] = s1[i];
        const float4* s2 = (const float4*)W2g; float4* d2 = (float4*)W2s;
        for (int i = tid; i < H_DIM * E_DIM / 4; i += THREADS) d2[i] = s2[i];
        if (tid < H_DIM) b1s[tid] = b1g[tid];
        if (tid < E_DIM) b2s[tid] = b2g[tid];
    }
    __syncthreads();

    const int rg = tid >> 4;        // 0..15 row group
    const int cg = tid & 15;        // 0..15 col group
    const int c0 = cg * 8;
    int rows[8];
    #pragma unroll
    for (int i = 0; i < 8; ++i) rows[i] = rg * 4 + (i & 3) + (i >> 2) * 64;

    float b1v[8], b2v[8];
    #pragma unroll
    for (int j = 0; j < 8; ++j) { b1v[j] = b1s[c0 + j]; b2v[j] = b2s[c0 + j]; }

    for (int t = blockIdx.x; t < numTiles; t += gridDim.x) {
        const int base = t * TILE_M;
        __syncthreads();   // previous tile's GEMM2 reads of AH must be done

        // Load A tile: x (cols 0..15) then h_node (cols 16..143)
        #pragma unroll
        for (int p = 0; p < (TILE_M * F_DIM / 4) / THREADS; ++p) {   // 2 passes
            int i = tid + p * THREADS;
            int r = i >> 2, c4 = i & 3;
            int gr = base + r;
            float4 v = make_float4(0.f, 0.f, 0.f, 0.f);
            if (gr < N) v = *(const float4*)(x + (size_t)gr * F_DIM + c4 * 4);
            *(float4*)&AH[r * A_PITCH + c4 * 4] = v;
        }
        #pragma unroll
        for (int p = 0; p < (TILE_M * E_DIM / 4) / THREADS; ++p) {   // 16 passes
            int i = tid + p * THREADS;
            int r = i >> 5, c4 = i & 31;
            int gr = base + r;
            float4 v = make_float4(0.f, 0.f, 0.f, 0.f);
            if (gr < N) v = *(const float4*)(hn + (size_t)gr * E_DIM + c4 * 4);
            *(float4*)&AH[r * A_PITCH + F_DIM + c4 * 4] = v;
        }
        __syncthreads();

        // GEMM1: [128,144] @ [144,128]
        u64 acc[8][4];
        #pragma unroll
        for (int i = 0; i < 8; ++i)
            #pragma unroll
            for (int j = 0; j < 4; ++j) acc[i][j] = 0ull;
        gemm_k<IN_DIM>(AH, W1s, rows, c0, acc);
        __syncthreads();   // all GEMM1 reads of AH done before overwrite

        // relu(acc + b1) -> AH (H1, reused buffer)
        #pragma unroll
        for (int i = 0; i < 8; ++i) {
            float o[8];
            #pragma unroll
            for (int j = 0; j < 4; ++j) {
                float2 p = unpack2(acc[i][j]);
                o[2*j]   = fmaxf(p.x + b1v[2*j],   0.f);
                o[2*j+1] = fmaxf(p.y + b1v[2*j+1], 0.f);
            }
            float* dst = &AH[rows[i] * A_PITCH + c0];
            *(float4*)dst       = make_float4(o[0], o[1], o[2], o[3]);
            *(float4*)(dst + 4) = make_float4(o[4], o[5], o[6], o[7]);
        }
        __syncthreads();

        // GEMM2: [128,128] @ [128,128]
        #pragma unroll
        for (int i = 0; i < 8; ++i)
            #pragma unroll
            for (int j = 0; j < 4; ++j) acc[i][j] = 0ull;
        gemm_k<H_DIM>(AH, W2s, rows, c0, acc);

        // Epilogue: +b2, run-length segment reduce, atomicAdd flush
        int segs[8];
        #pragma unroll
        for (int i = 0; i < 8; ++i) {
            int gr = base + rows[i];
            segs[i] = (gr < N) ? g_seg_arr[gr] : -1;
        }
        float run[8];
        #pragma unroll
        for (int j = 0; j < 8; ++j) run[j] = 0.f;
        int cur = segs[0];
        #pragma unroll
        for (int i = 0; i < 8; ++i) {
            if (segs[i] != cur) {
                if (cur >= 0) {
                    float* o = out + (size_t)cur * E_DIM + c0;
                    #pragma unroll
                    for (int j = 0; j < 8; ++j) atomicAdd(o + j, run[j]);
                }
                cur = segs[i];
                #pragma unroll
                for (int j = 0; j < 8; ++j) run[j] = 0.f;
            }
            if (segs[i] >= 0) {
                #pragma unroll
                for (int j = 0; j < 4; ++j) {
                    float2 p = unpack2(acc[i][j]);
                    run[2*j]   += p.x + b2v[2*j];
                    run[2*j+1] += p.y + b2v[2*j+1];
                }
            }
        }
        if (cur >= 0) {
            float* o = out + (size_t)cur * E_DIM + c0;
            #pragma unroll
            for (int j = 0; j < 8; ++j) atomicAdd(o + j, run[j]);
        }
    }
}

// ---------------- launch ----------------
extern "C" void kernel_launch(void* const* d_in, const int* in_sizes, int n_in,
                              void* d_out, int out_size) {
    const float* x  = (const float*)d_in[0];
    const float* hn = (const float*)d_in[1];
    const void*  pt = d_in[2];
    const float* W1 = (const float*)d_in[3];
    const float* b1 = (const float*)d_in[4];
    const float* W2 = (const float*)d_in[5];
    const float* b2 = (const float*)d_in[6];
    float* out = (float*)d_out;

    int N    = in_sizes[0] / F_DIM;       // x is [N, 16]
    int Bseg = in_sizes[2] - 1;           // ptr has B+1 entries

    int prep_n = (out_size > Bseg + 1) ? out_size : (Bseg + 1);
    prep_kernel<<<(prep_n + 255) / 256, 256>>>(pt, out, out_size, Bseg, N);
    seg_kernel<<<(N + 255) / 256, 256>>>(N, Bseg);

    int numTiles = (N + TILE_M - 1) / TILE_M;
    int smem_bytes = (IN_DIM * H_DIM + H_DIM * E_DIM + H_DIM + E_DIM
                      + TILE_M * A_PITCH) * (int)sizeof(float);
    cudaFuncSetAttribute(fused_kernel, cudaFuncAttributeMaxDynamicSharedMemorySize,
                         smem_bytes);
    int sms = 0;
    cudaDeviceGetAttribute(&sms, cudaDevAttrMultiProcessorCount, 0);
    if (sms <= 0) sms = 148;
    int grid = (sms < numTiles) ? sms : numTiles;
    fused_kernel<<<grid, THREADS, smem_bytes>>>(x, hn, W1, b1, W2, b2, out, N, numTiles);
}

// round 3
// speedup vs baseline: 2.4053x; 2.4053x over previous
#include <cuda_runtime.h>
#include <cuda_bf16.h>
#include <cstdint>

#define THREADS 256

// smem layout (bytes)
#define W1F_OFF 0            // [9 kb][16 nb][32 lane] uint4 (b0h,b1h,b0l,b1l)
#define W2F_OFF 73728        // [8][16][32] uint4
#define B1_OFF  139264
#define B2_OFF  139776
#define SMEM_BYTES 140288

__device__ int g_seg_arr[2000256];
__device__ int g_ptr32[33024];

// split fp32 pair -> bf16x2 hi + bf16x2 lo (v0 in low half, v1 in high half)
__device__ __forceinline__ void split2(float a0, float a1, uint32_t& h2, uint32_t& l2) {
    asm("cvt.rn.bf16x2.f32 %0, %1, %2;" : "=r"(h2) : "f"(a1), "f"(a0));
    float h0 = __uint_as_float(h2 << 16);
    float h1 = __uint_as_float(h2 & 0xffff0000u);
    float r0 = a0 - h0, r1 = a1 - h1;
    asm("cvt.rn.bf16x2.f32 %0, %1, %2;" : "=r"(l2) : "f"(r1), "f"(r0));
}

__device__ __forceinline__ void mma_bf16(float c[4], const uint32_t a[4],
                                         uint32_t b0, uint32_t b1) {
    asm volatile("mma.sync.aligned.m16n8k16.row.col.f32.bf16.bf16.f32 "
                 "{%0,%1,%2,%3}, {%4,%5,%6,%7}, {%8,%9}, {%0,%1,%2,%3};"
                 : "+f"(c[0]), "+f"(c[1]), "+f"(c[2]), "+f"(c[3])
                 : "r"(a[0]), "r"(a[1]), "r"(a[2]), "r"(a[3]), "r"(b0), "r"(b1));
}

// ---------------- prep: zero output + normalize ptr to int32 ----------------
__global__ void prep_kernel(const void* __restrict__ ptr_raw, float* __restrict__ out,
                            int out_elems, int Bseg, int N) {
    int idx = blockIdx.x * blockDim.x + threadIdx.x;
    if (idx < out_elems) out[idx] = 0.0f;
    if (idx <= Bseg) {
        const int* p32 = (const int*)ptr_raw;
        bool is64 = (p32[Bseg] != N);
        int v = is64 ? (int)(((const long long*)ptr_raw)[idx]) : p32[idx];
        g_ptr32[idx] = v;
    }
}
__global__ void seg_kernel(int N, int Bseg) {
    int i = blockIdx.x * blockDim.x + threadIdx.x;
    if (i >= N) return;
    int lo = 0, hi = Bseg + 1;
    while (lo < hi) { int mid = (lo + hi) >> 1; if (g_ptr32[mid] <= i) lo = mid + 1; else hi = mid; }
    g_seg_arr[i] = lo - 1;
}

// ---------------- fused MLP + segment-sum via mma.sync bf16 ----------------
__global__ __launch_bounds__(THREADS, 1)
void fused_mma(const float* __restrict__ x, const float* __restrict__ hn,
               const float* __restrict__ W1g, const float* __restrict__ b1g,
               const float* __restrict__ W2g, const float* __restrict__ b2g,
               float* __restrict__ out, int N) {
    extern __shared__ char smc[];
    uint4* W1F = (uint4*)(smc + W1F_OFF);
    uint4* W2F = (uint4*)(smc + W2F_OFF);
    float* b1s = (float*)(smc + B1_OFF);
    float* b2s = (float*)(smc + B2_OFF);

    const int tid = threadIdx.x;
    const int lane = tid & 31;
    const int wid = tid >> 5;

    // ---- build B-fragment images in smem (once) ----
    for (int s = tid; s < 9 * 16 * 32; s += THREADS) {
        int kb = s >> 9, nb = (s >> 5) & 15, ln = s & 31;
        int k0 = kb * 16 + 2 * (ln & 3);
        int n  = nb * 8 + (ln >> 2);
        float w00 = W1g[k0 * 128 + n],       w01 = W1g[(k0 + 1) * 128 + n];
        float w10 = W1g[(k0 + 8) * 128 + n], w11 = W1g[(k0 + 9) * 128 + n];
        uint32_t b0h, b0l, b1h, b1l;
        split2(w00, w01, b0h, b0l);
        split2(w10, w11, b1h, b1l);
        W1F[s] = make_uint4(b0h, b1h, b0l, b1l);
    }
    for (int s = tid; s < 8 * 16 * 32; s += THREADS) {
        int kb = s >> 9, nb = (s >> 5) & 15, ln = s & 31;
        int k0 = kb * 16 + 2 * (ln & 3);
        int n  = nb * 8 + (ln >> 2);
        float w00 = W2g[k0 * 128 + n],       w01 = W2g[(k0 + 1) * 128 + n];
        float w10 = W2g[(k0 + 8) * 128 + n], w11 = W2g[(k0 + 9) * 128 + n];
        uint32_t b0h, b0l, b1h, b1l;
        split2(w00, w01, b0h, b0l);
        split2(w10, w11, b1h, b1l);
        W2F[s] = make_uint4(b0h, b1h, b0l, b1l);
    }
    if (tid < 128) { b1s[tid] = b1g[tid]; b2s[tid] = b2g[tid]; }
    __syncthreads();

    const int c0 = 2 * (lane & 3);      // col pair within 8-col n-block
    const int rq = lane >> 2;           // row within 8-row half
    const int totalWarps = gridDim.x * (THREADS / 32);
    const int wgid = blockIdx.x * (THREADS / 32) + wid;
    const int nChunks = (N + 15) >> 4;
    const unsigned FM = 0xffffffffu;

    for (int ch = wgid; ch < nChunks; ch += totalWarps) {
        const int base = ch << 4;
        const int gr0 = base + rq, gr1 = gr0 + 8;
        const bool ok0 = gr0 < N, ok1 = gr1 < N;

        float acc[16][4];
        #pragma unroll
        for (int i = 0; i < 16; ++i)
            #pragma unroll
            for (int j = 0; j < 4; ++j) acc[i][j] = 0.f;

        // ---------------- GEMM1: K = 144 (kb0 = x, kb1..8 = hn) ----------------
        #pragma unroll 1
        for (int kb = 0; kb < 9; ++kb) {
            const float* p0;
            const float* p1;
            if (kb == 0) { p0 = x + (size_t)gr0 * 16; p1 = x + (size_t)gr1 * 16; }
            else { p0 = hn + (size_t)gr0 * 128 + (kb - 1) * 16;
                   p1 = hn + (size_t)gr1 * 128 + (kb - 1) * 16; }
            float2 z2 = make_float2(0.f, 0.f);
            float2 f00 = ok0 ? *(const float2*)(p0 + c0)     : z2;
            float2 f01 = ok0 ? *(const float2*)(p0 + c0 + 8) : z2;
            float2 f10 = ok1 ? *(const float2*)(p1 + c0)     : z2;
            float2 f11 = ok1 ? *(const float2*)(p1 + c0 + 8) : z2;
            uint32_t ah[4], al[4];
            split2(f00.x, f00.y, ah[0], al[0]);
            split2(f10.x, f10.y, ah[1], al[1]);
            split2(f01.x, f01.y, ah[2], al[2]);
            split2(f11.x, f11.y, ah[3], al[3]);
            const uint4* wrow = W1F + kb * 16 * 32 + lane;
            #pragma unroll
            for (int g = 0; g < 4; ++g) {
                uint4 B[4];
                #pragma unroll
                for (int j = 0; j < 4; ++j) B[j] = wrow[(g * 4 + j) * 32];
                #pragma unroll
                for (int j = 0; j < 4; ++j) mma_bf16(acc[g * 4 + j], ah, B[j].x, B[j].y);
                #pragma unroll
                for (int j = 0; j < 4; ++j) mma_bf16(acc[g * 4 + j], al, B[j].x, B[j].y);
                #pragma unroll
                for (int j = 0; j < 4; ++j) mma_bf16(acc[g * 4 + j], ah, B[j].z, B[j].w);
            }
        }

        // ---------------- epilogue1: bias + relu + split -> H frags ----------------
        uint32_t hh[8][4], hl[8][4];
        #pragma unroll
        for (int kb2 = 0; kb2 < 8; ++kb2) {
            #pragma unroll
            for (int hf = 0; hf < 2; ++hf) {
                int nb = 2 * kb2 + hf;
                float bb0 = b1s[nb * 8 + c0], bb1 = b1s[nb * 8 + c0 + 1];
                float q0 = fmaxf(acc[nb][0] + bb0, 0.f);
                float q1 = fmaxf(acc[nb][1] + bb1, 0.f);
                float q2 = fmaxf(acc[nb][2] + bb0, 0.f);
                float q3 = fmaxf(acc[nb][3] + bb1, 0.f);
                split2(q0, q1, hh[kb2][2 * hf],     hl[kb2][2 * hf]);
                split2(q2, q3, hh[kb2][2 * hf + 1], hl[kb2][2 * hf + 1]);
            }
        }

        #pragma unroll
        for (int i = 0; i < 16; ++i)
            #pragma unroll
            for (int j = 0; j < 4; ++j) acc[i][j] = 0.f;

        // ---------------- GEMM2: K = 128, A = H (registers) ----------------
        #pragma unroll
        for (int kb = 0; kb < 8; ++kb) {
            const uint4* wrow = W2F + kb * 16 * 32 + lane;
            #pragma unroll
            for (int g = 0; g < 4; ++g) {
                uint4 B[4];
                #pragma unroll
                for (int j = 0; j < 4; ++j) B[j] = wrow[(g * 4 + j) * 32];
                #pragma unroll
                for (int j = 0; j < 4; ++j) mma_bf16(acc[g * 4 + j], hh[kb], B[j].x, B[j].y);
                #pragma unroll
                for (int j = 0; j < 4; ++j) mma_bf16(acc[g * 4 + j], hl[kb], B[j].x, B[j].y);
                #pragma unroll
                for (int j = 0; j < 4; ++j) mma_bf16(acc[g * 4 + j], hh[kb], B[j].z, B[j].w);
            }
        }

        // ---------------- epilogue2: bias + segmented reduce + atomics ----------------
        int s0 = ok0 ? g_seg_arr[gr0] : -1;
        int s1 = ok1 ? g_seg_arr[gr1] : -1;
        bool m0[3], m1[3];
        #pragma unroll
        for (int d = 0; d < 3; ++d) {
            int dd = 1 << d;
            int t0 = __shfl_down_sync(FM, s0, 4 * dd);
            int t1 = __shfl_down_sync(FM, s1, 4 * dd);
            m0[d] = (rq + dd < 8) && (t0 == s0);
            m1[d] = (rq + dd < 8) && (t1 == s1);
        }
        int p0s = __shfl_up_sync(FM, s0, 4);
        int p1s = __shfl_up_sync(FM, s1, 4);
        bool lead0 = (rq == 0) || (p0s != s0);
        bool lead1 = (rq == 0) || (p1s != s1);

        #pragma unroll
        for (int nb = 0; nb < 16; ++nb) {
            float bb0 = b2s[nb * 8 + c0], bb1 = b2s[nb * 8 + c0 + 1];
            float v0 = ok0 ? acc[nb][0] + bb0 : 0.f;
            float v1 = ok0 ? acc[nb][1] + bb1 : 0.f;
            float v2 = ok1 ? acc[nb][2] + bb0 : 0.f;
            float v3 = ok1 ? acc[nb][3] + bb1 : 0.f;
            #pragma unroll
            for (int d = 0; d < 3; ++d) {
                int dd = 4 << d;
                float t;
                t = __shfl_down_sync(FM, v0, dd); if (m0[d]) v0 += t;
                t = __shfl_down_sync(FM, v1, dd); if (m0[d]) v1 += t;
                t = __shfl_down_sync(FM, v2, dd); if (m1[d]) v2 += t;
                t = __shfl_down_sync(FM, v3, dd); if (m1[d]) v3 += t;
            }
            if (lead0 && s0 >= 0) {
                float* o = out + (size_t)s0 * 128 + nb * 8 + c0;
                atomicAdd(o,     v0);
                atomicAdd(o + 1, v1);
            }
            if (lead1 && s1 >= 0) {
                float* o = out + (size_t)s1 * 128 + nb * 8 + c0;
                atomicAdd(o,     v2);
                atomicAdd(o + 1, v3);
            }
        }
    }
}

// ---------------- launch ----------------
extern "C" void kernel_launch(void* const* d_in, const int* in_sizes, int n_in,
                              void* d_out, int out_size) {
    const float* x  = (const float*)d_in[0];
    const float* hn = (const float*)d_in[1];
    const void*  pt = d_in[2];
    const float* W1 = (const float*)d_in[3];
    const float* b1 = (const float*)d_in[4];
    const float* W2 = (const float*)d_in[5];
    const float* b2 = (const float*)d_in[6];
    float* out = (float*)d_out;

    int N    = in_sizes[0] / 16;
    int Bseg = in_sizes[2] - 1;

    int prep_n = (out_size > Bseg + 1) ? out_size : (Bseg + 1);
    prep_kernel<<<(prep_n + 255) / 256, 256>>>(pt, out, out_size, Bseg, N);
    seg_kernel<<<(N + 255) / 256, 256>>>(N, Bseg);

    cudaFuncSetAttribute(fused_mma, cudaFuncAttributeMaxDynamicSharedMemorySize, SMEM_BYTES);
    int sms = 0;
    cudaDeviceGetAttribute(&sms, cudaDevAttrMultiProcessorCount, 0);
    if (sms <= 0) sms = 148;
    int nChunks = (N + 15) >> 4;
    int maxCtas = (nChunks + 7) / 8;
    int grid = (sms < maxCtas) ? sms : maxCtas;
    fused_mma<<<grid, THREADS, SMEM_BYTES>>>(x, hn, W1, b1, W2, b2, out, N);
}

// round 4
// speedup vs baseline: 3.4639x; 1.4401x over previous
#include <cuda_runtime.h>
#include <cuda_fp16.h>
#include <cstdint>

#define THREADS 256

// smem layout (bytes)
#define W1F_OFF 0          // [9 kb][16 nb][32 lane] uint2 (b0h,b1h) fp16x2
#define W2F_OFF 36864      // [8][16][32] uint2
#define B1_OFF  69632
#define B2_OFF  70144
#define SMEM_BYTES 70656

__device__ int g_seg_arr[2000256];

// pack two f32 -> f16x2 (a0 low, a1 high)
__device__ __forceinline__ uint32_t packh(float a0, float a1) {
    uint32_t r;
    asm("cvt.rn.f16x2.f32 %0, %1, %2;" : "=r"(r) : "f"(a1), "f"(a0));
    return r;
}
// split: h2 = fp16x2(a0,a1), l2 = fp16x2 of residuals
__device__ __forceinline__ void split2h(float a0, float a1, uint32_t& h2, uint32_t& l2) {
    asm("cvt.rn.f16x2.f32 %0, %1, %2;" : "=r"(h2) : "f"(a1), "f"(a0));
    __half2 hv = *reinterpret_cast<__half2*>(&h2);
    float r0 = a0 - __low2float(hv);
    float r1 = a1 - __high2float(hv);
    asm("cvt.rn.f16x2.f32 %0, %1, %2;" : "=r"(l2) : "f"(r1), "f"(r0));
}

__device__ __forceinline__ void mma_f16(float* c, const uint32_t* a, uint32_t b0, uint32_t b1) {
    asm volatile("mma.sync.aligned.m16n8k16.row.col.f32.f16.f16.f32 "
                 "{%0,%1,%2,%3}, {%4,%5,%6,%7}, {%8,%9}, {%0,%1,%2,%3};"
                 : "+f"(c[0]), "+f"(c[1]), "+f"(c[2]), "+f"(c[3])
                 : "r"(a[0]), "r"(a[1]), "r"(a[2]), "r"(a[3]), "r"(b0), "r"(b1));
}

// ---------------- prep: zero output + seg ids (single kernel) ----------------
__global__ void prep_kernel(const void* __restrict__ ptr_raw, float4* __restrict__ out4,
                            int out4_elems, int Bseg, int N) {
    int idx = blockIdx.x * blockDim.x + threadIdx.x;
    if (idx < out4_elems) out4[idx] = make_float4(0.f, 0.f, 0.f, 0.f);
    if (idx < N) {
        const int* p32 = (const int*)ptr_raw;
        const long long* p64 = (const long long*)ptr_raw;
        bool is64 = (p32[Bseg] != N);
        int lo = 0, hi = Bseg + 1;
        while (lo < hi) {
            int mid = (lo + hi) >> 1;
            long long v = is64 ? p64[mid] : (long long)p32[mid];
            if (v <= (long long)idx) lo = mid + 1; else hi = mid;
        }
        g_seg_arr[idx] = lo - 1;
    }
}

// ---------------- fused MLP + segment-sum: fp16 2-term, M=32/warp ----------------
__global__ __launch_bounds__(THREADS, 1)
void fused_mma(const float* __restrict__ x, const float* __restrict__ hn,
               const float* __restrict__ W1g, const float* __restrict__ b1g,
               const float* __restrict__ W2g, const float* __restrict__ b2g,
               float* __restrict__ out, int N) {
    extern __shared__ char smc[];
    uint2* W1F = (uint2*)(smc + W1F_OFF);
    uint2* W2F = (uint2*)(smc + W2F_OFF);
    float* b1s = (float*)(smc + B1_OFF);
    float* b2s = (float*)(smc + B2_OFF);

    const int tid  = threadIdx.x;
    const int lane = tid & 31;
    const int wid  = tid >> 5;

    // ---- build fp16 B-fragment images in smem (once) ----
    for (int s = tid; s < 9 * 16 * 32; s += THREADS) {
        int kb = s >> 9, nb = (s >> 5) & 15, ln = s & 31;
        int k0 = kb * 16 + 2 * (ln & 3);
        int n  = nb * 8 + (ln >> 2);
        uint32_t b0 = packh(W1g[k0 * 128 + n],       W1g[(k0 + 1) * 128 + n]);
        uint32_t b1 = packh(W1g[(k0 + 8) * 128 + n], W1g[(k0 + 9) * 128 + n]);
        W1F[s] = make_uint2(b0, b1);
    }
    for (int s = tid; s < 8 * 16 * 32; s += THREADS) {
        int kb = s >> 9, nb = (s >> 5) & 15, ln = s & 31;
        int k0 = kb * 16 + 2 * (ln & 3);
        int n  = nb * 8 + (ln >> 2);
        uint32_t b0 = packh(W2g[k0 * 128 + n],       W2g[(k0 + 1) * 128 + n]);
        uint32_t b1 = packh(W2g[(k0 + 8) * 128 + n], W2g[(k0 + 9) * 128 + n]);
        W2F[s] = make_uint2(b0, b1);
    }
    if (tid < 128) { b1s[tid] = b1g[tid]; b2s[tid] = b2g[tid]; }
    __syncthreads();

    const int rq = lane >> 2;           // row within 8-row group
    const int c0 = 2 * (lane & 3);      // col pair within 8-col n-block
    const int totalWarps = gridDim.x * (THREADS / 32);
    const int wgid = blockIdx.x * (THREADS / 32) + wid;
    const int nIters = (N + 31) >> 5;
    const unsigned FM = 0xffffffffu;

    for (int it = wgid; it < nIters; it += totalWarps) {
        const int base = it << 5;
        int gr[4]; bool ok[4];
        #pragma unroll
        for (int r = 0; r < 4; ++r) { gr[r] = base + r * 8 + rq; ok[r] = gr[r] < N; }

        // seg ids + masks (chunk c = rows [16c,16c+16); groups g = 8-row halves)
        int sg[2][2]; bool mk[2][2][3]; bool ld[2][2];
        #pragma unroll
        for (int c = 0; c < 2; ++c) {
            #pragma unroll
            for (int g = 0; g < 2; ++g) {
                int r = 2 * c + g;
                int s = ok[r] ? g_seg_arr[gr[r]] : -1;
                sg[c][g] = s;
                #pragma unroll
                for (int d = 0; d < 3; ++d) {
                    int t = __shfl_down_sync(FM, s, 4 << d);
                    mk[c][g][d] = (rq + (1 << d) < 8) && (t == s);
                }
                int pu = __shfl_up_sync(FM, s, 4);
                ld[c][g] = (rq == 0) || (pu != s);
            }
        }

        float acc1[2][16][4];
        #pragma unroll
        for (int c = 0; c < 2; ++c)
            #pragma unroll
            for (int nb = 0; nb < 16; ++nb)
                #pragma unroll
                for (int j = 0; j < 4; ++j) acc1[c][nb][j] = 0.f;

        // ---- GEMM1: K=144 (kb0 = x, kb1..8 = hn), distance-1 prefetch ----
        float2 buf[4][2];
        const float2 z2 = make_float2(0.f, 0.f);
        #pragma unroll
        for (int r = 0; r < 4; ++r) {
            const float* p = x + (size_t)gr[r] * 16;
            buf[r][0] = ok[r] ? *(const float2*)(p + c0)     : z2;
            buf[r][1] = ok[r] ? *(const float2*)(p + c0 + 8) : z2;
        }
        #pragma unroll
        for (int kb = 0; kb < 9; ++kb) {
            float2 nbuf[4][2];
            if (kb < 8) {
                #pragma unroll
                for (int r = 0; r < 4; ++r) {
                    const float* p = hn + (size_t)gr[r] * 128 + kb * 16;
                    nbuf[r][0] = ok[r] ? *(const float2*)(p + c0)     : z2;
                    nbuf[r][1] = ok[r] ? *(const float2*)(p + c0 + 8) : z2;
                }
            }
            uint32_t ah[2][4], al[2][4];
            #pragma unroll
            for (int c = 0; c < 2; ++c) {
                split2h(buf[2*c][0].x,   buf[2*c][0].y,   ah[c][0], al[c][0]);
                split2h(buf[2*c+1][0].x, buf[2*c+1][0].y, ah[c][1], al[c][1]);
                split2h(buf[2*c][1].x,   buf[2*c][1].y,   ah[c][2], al[c][2]);
                split2h(buf[2*c+1][1].x, buf[2*c+1][1].y, ah[c][3], al[c][3]);
            }
            const uint2* w = W1F + kb * 512 + lane;
            #pragma unroll
            for (int nb = 0; nb < 16; ++nb) {
                uint2 b = w[nb * 32];
                mma_f16(acc1[0][nb], ah[0], b.x, b.y);
                mma_f16(acc1[0][nb], al[0], b.x, b.y);
                mma_f16(acc1[1][nb], ah[1], b.x, b.y);
                mma_f16(acc1[1][nb], al[1], b.x, b.y);
            }
            #pragma unroll
            for (int r = 0; r < 4; ++r) { buf[r][0] = nbuf[r][0]; buf[r][1] = nbuf[r][1]; }
        }

        // ---- epilogue1: bias + relu + fp16 split -> H fragments (registers) ----
        uint32_t hh[2][8][4], hl[2][8][4];
        #pragma unroll
        for (int c = 0; c < 2; ++c) {
            #pragma unroll
            for (int kb2 = 0; kb2 < 8; ++kb2) {
                int nb0 = 2 * kb2, nb1 = nb0 + 1;
                float bb00 = b1s[nb0 * 8 + c0], bb01 = b1s[nb0 * 8 + c0 + 1];
                float bb10 = b1s[nb1 * 8 + c0], bb11 = b1s[nb1 * 8 + c0 + 1];
                split2h(fmaxf(acc1[c][nb0][0] + bb00, 0.f), fmaxf(acc1[c][nb0][1] + bb01, 0.f),
                        hh[c][kb2][0], hl[c][kb2][0]);
                split2h(fmaxf(acc1[c][nb0][2] + bb00, 0.f), fmaxf(acc1[c][nb0][3] + bb01, 0.f),
                        hh[c][kb2][1], hl[c][kb2][1]);
                split2h(fmaxf(acc1[c][nb1][0] + bb10, 0.f), fmaxf(acc1[c][nb1][1] + bb11, 0.f),
                        hh[c][kb2][2], hl[c][kb2][2]);
                split2h(fmaxf(acc1[c][nb1][2] + bb10, 0.f), fmaxf(acc1[c][nb1][3] + bb11, 0.f),
                        hh[c][kb2][3], hl[c][kb2][3]);
            }
        }

        // ---- GEMM2 (K=128) in two N-halves + fused epilogue2 ----
        #pragma unroll
        for (int nh = 0; nh < 2; ++nh) {
            float acc2[2][8][4];
            #pragma unroll
            for (int c = 0; c < 2; ++c)
                #pragma unroll
                for (int nb = 0; nb < 8; ++nb)
                    #pragma unroll
                    for (int j = 0; j < 4; ++j) acc2[c][nb][j] = 0.f;

            #pragma unroll
            for (int kb2 = 0; kb2 < 8; ++kb2) {
                const uint2* w = W2F + kb2 * 512 + nh * 256 + lane;
                #pragma unroll
                for (int nbl = 0; nbl < 8; ++nbl) {
                    uint2 b = w[nbl * 32];
                    mma_f16(acc2[0][nbl], hh[0][kb2], b.x, b.y);
                    mma_f16(acc2[0][nbl], hl[0][kb2], b.x, b.y);
                    mma_f16(acc2[1][nbl], hh[1][kb2], b.x, b.y);
                    mma_f16(acc2[1][nbl], hl[1][kb2], b.x, b.y);
                }
            }

            // bias + segmented shfl-reduce + atomics
            #pragma unroll
            for (int c = 0; c < 2; ++c) {
                #pragma unroll
                for (int nbl = 0; nbl < 8; ++nbl) {
                    int nb = nh * 8 + nbl;
                    float bb0 = b2s[nb * 8 + c0], bb1 = b2s[nb * 8 + c0 + 1];
                    float v0 = acc2[c][nbl][0] + bb0;
                    float v1 = acc2[c][nbl][1] + bb1;
                    float v2 = acc2[c][nbl][2] + bb0;
                    float v3 = acc2[c][nbl][3] + bb1;
                    #pragma unroll
                    for (int d = 0; d < 3; ++d) {
                        int dd = 4 << d;
                        float t;
                        t = __shfl_down_sync(FM, v0, dd); if (mk[c][0][d]) v0 += t;
                        t = __shfl_down_sync(FM, v1, dd); if (mk[c][0][d]) v1 += t;
                        t = __shfl_down_sync(FM, v2, dd); if (mk[c][1][d]) v2 += t;
                        t = __shfl_down_sync(FM, v3, dd); if (mk[c][1][d]) v3 += t;
                    }
                    if (ld[c][0] && sg[c][0] >= 0) {
                        float* o = out + (size_t)sg[c][0] * 128 + nb * 8 + c0;
                        atomicAdd(o,     v0);
                        atomicAdd(o + 1, v1);
                    }
                    if (ld[c][1] && sg[c][1] >= 0) {
                        float* o = out + (size_t)sg[c][1] * 128 + nb * 8 + c0;
                        atomicAdd(o,     v2);
                        atomicAdd(o + 1, v3);
                    }
                }
            }
        }
    }
}

// ---------------- launch ----------------
extern "C" void kernel_launch(void* const* d_in, const int* in_sizes, int n_in,
                              void* d_out, int out_size) {
    const float* x  = (const float*)d_in[0];
    const float* hn = (const float*)d_in[1];
    const void*  pt = d_in[2];
    const float* W1 = (const float*)d_in[3];
    const float* b1 = (const float*)d_in[4];
    const float* W2 = (const float*)d_in[5];
    const float* b2 = (const float*)d_in[6];
    float* out = (float*)d_out;

    int N    = in_sizes[0] / 16;
    int Bseg = in_sizes[2] - 1;

    int out4 = out_size / 4;
    int prep_n = (out4 > N) ? out4 : N;
    prep_kernel<<<(prep_n + 255) / 256, 256>>>(pt, (float4*)out, out4, Bseg, N);

    cudaFuncSetAttribute(fused_mma, cudaFuncAttributeMaxDynamicSharedMemorySize, SMEM_BYTES);
    int sms = 0;
    cudaDeviceGetAttribute(&sms, cudaDevAttrMultiProcessorCount, 0);
    if (sms <= 0) sms = 148;
    int nIters = (N + 31) >> 5;
    int maxCtas = (nIters + 7) / 8;
    int grid = (sms < maxCtas) ? sms : maxCtas;
    fused_mma<<<grid, THREADS, SMEM_BYTES>>>(x, hn, W1, b1, W2, b2, out, N);
}

// round 5
// speedup vs baseline: 4.4824x; 1.2940x over previous
#include <cuda_runtime.h>
#include <cuda_fp16.h>
#include <cstdint>

#define THREADS 128

// smem layout (bytes)
#define W1F_OFF 0          // [9 kb][16 nb][32 lane] uint2 (b0h,b1h) fp16x2
#define W2F_OFF 36864      // [8][16][32] uint2
#define B1_OFF  69632
#define B2_OFF  70144
#define SMEM_BYTES 70656

__device__ int g_seg_arr[2000256];

// pack two f32 -> f16x2 (a0 low, a1 high)
__device__ __forceinline__ uint32_t packh(float a0, float a1) {
    uint32_t r;
    asm("cvt.rn.f16x2.f32 %0, %1, %2;" : "=r"(r) : "f"(a1), "f"(a0));
    return r;
}

__device__ __forceinline__ void mma_f16(float* c, const uint32_t* a, uint32_t b0, uint32_t b1) {
    asm volatile("mma.sync.aligned.m16n8k16.row.col.f32.f16.f16.f32 "
                 "{%0,%1,%2,%3}, {%4,%5,%6,%7}, {%8,%9}, {%0,%1,%2,%3};"
                 : "+f"(c[0]), "+f"(c[1]), "+f"(c[2]), "+f"(c[3])
                 : "r"(a[0]), "r"(a[1]), "r"(a[2]), "r"(a[3]), "r"(b0), "r"(b1));
}

// ---------------- prep: zero output + seg ids (single kernel) ----------------
__global__ void prep_kernel(const void* __restrict__ ptr_raw, float4* __restrict__ out4,
                            int out4_elems, int Bseg, int N) {
    int idx = blockIdx.x * blockDim.x + threadIdx.x;
    if (idx < out4_elems) out4[idx] = make_float4(0.f, 0.f, 0.f, 0.f);
    if (idx < N) {
        const int* p32 = (const int*)ptr_raw;
        const long long* p64 = (const long long*)ptr_raw;
        bool is64 = (p32[Bseg] != N);
        int lo = 0, hi = Bseg + 1;
        while (lo < hi) {
            int mid = (lo + hi) >> 1;
            long long v = is64 ? p64[mid] : (long long)p32[mid];
            if (v <= (long long)idx) lo = mid + 1; else hi = mid;
        }
        g_seg_arr[idx] = lo - 1;
    }
}

// ---------------- fused MLP + segment-sum: fp16 1-term, M=32/warp ----------------
__global__ __launch_bounds__(THREADS, 3)
void fused_mma(const float* __restrict__ x, const float* __restrict__ hn,
               const float* __restrict__ W1g, const float* __restrict__ b1g,
               const float* __restrict__ W2g, const float* __restrict__ b2g,
               float* __restrict__ out, int N) {
    extern __shared__ char smc[];
    uint2* W1F = (uint2*)(smc + W1F_OFF);
    uint2* W2F = (uint2*)(smc + W2F_OFF);
    float* b1s = (float*)(smc + B1_OFF);
    float* b2s = (float*)(smc + B2_OFF);

    const int tid  = threadIdx.x;
    const int lane = tid & 31;
    const int wid  = tid >> 5;

    // ---- build fp16 B-fragment images in smem (once per CTA) ----
    for (int s = tid; s < 9 * 16 * 32; s += THREADS) {
        int kb = s >> 9, nb = (s >> 5) & 15, ln = s & 31;
        int k0 = kb * 16 + 2 * (ln & 3);
        int n  = nb * 8 + (ln >> 2);
        uint32_t b0 = packh(W1g[k0 * 128 + n],       W1g[(k0 + 1) * 128 + n]);
        uint32_t b1 = packh(W1g[(k0 + 8) * 128 + n], W1g[(k0 + 9) * 128 + n]);
        W1F[s] = make_uint2(b0, b1);
    }
    for (int s = tid; s < 8 * 16 * 32; s += THREADS) {
        int kb = s >> 9, nb = (s >> 5) & 15, ln = s & 31;
        int k0 = kb * 16 + 2 * (ln & 3);
        int n  = nb * 8 + (ln >> 2);
        uint32_t b0 = packh(W2g[k0 * 128 + n],       W2g[(k0 + 1) * 128 + n]);
        uint32_t b1 = packh(W2g[(k0 + 8) * 128 + n], W2g[(k0 + 9) * 128 + n]);
        W2F[s] = make_uint2(b0, b1);
    }
    if (tid < 128) { b1s[tid] = b1g[tid]; b2s[tid] = b2g[tid]; }
    __syncthreads();

    const int rq = lane >> 2;           // row within 8-row group
    const int c0 = 2 * (lane & 3);      // col pair within 8-col n-block
    const int totalWarps = gridDim.x * (THREADS / 32);
    const int wgid = blockIdx.x * (THREADS / 32) + wid;
    const int nIters = (N + 31) >> 5;
    const unsigned FM = 0xffffffffu;
    const float2 z2 = make_float2(0.f, 0.f);

    for (int it = wgid; it < nIters; it += totalWarps) {
        const int base = it << 5;
        int gr[4]; bool ok[4];
        #pragma unroll
        for (int r = 0; r < 4; ++r) { gr[r] = base + r * 8 + rq; ok[r] = gr[r] < N; }

        uint32_t hh[2][8][4];   // H fragments (fp16x2), built across two GEMM1 passes

        // ---- GEMM1: two N-half passes (A re-read; 2nd pass hits L1/L2) ----
        #pragma unroll
        for (int hf = 0; hf < 2; ++hf) {
            float acc1[2][8][4];
            #pragma unroll
            for (int c = 0; c < 2; ++c)
                #pragma unroll
                for (int nb = 0; nb < 8; ++nb)
                    #pragma unroll
                    for (int j = 0; j < 4; ++j) acc1[c][nb][j] = 0.f;

            float2 buf[4][2];
            #pragma unroll
            for (int r = 0; r < 4; ++r) {
                const float* p = x + (size_t)gr[r] * 16;
                buf[r][0] = ok[r] ? *(const float2*)(p + c0)     : z2;
                buf[r][1] = ok[r] ? *(const float2*)(p + c0 + 8) : z2;
            }
            #pragma unroll
            for (int kb = 0; kb < 9; ++kb) {
                float2 nbuf[4][2];
                if (kb < 8) {
                    #pragma unroll
                    for (int r = 0; r < 4; ++r) {
                        const float* p = hn + (size_t)gr[r] * 128 + kb * 16;
                        nbuf[r][0] = ok[r] ? *(const float2*)(p + c0)     : z2;
                        nbuf[r][1] = ok[r] ? *(const float2*)(p + c0 + 8) : z2;
                    }
                }
                uint32_t ah[2][4];
                #pragma unroll
                for (int c = 0; c < 2; ++c) {
                    ah[c][0] = packh(buf[2*c][0].x,   buf[2*c][0].y);
                    ah[c][1] = packh(buf[2*c+1][0].x, buf[2*c+1][0].y);
                    ah[c][2] = packh(buf[2*c][1].x,   buf[2*c][1].y);
                    ah[c][3] = packh(buf[2*c+1][1].x, buf[2*c+1][1].y);
                }
                const uint2* w = W1F + kb * 512 + hf * 256 + lane;
                #pragma unroll
                for (int nbl = 0; nbl < 8; ++nbl) {
                    uint2 b = w[nbl * 32];
                    mma_f16(acc1[0][nbl], ah[0], b.x, b.y);
                    mma_f16(acc1[1][nbl], ah[1], b.x, b.y);
                }
                #pragma unroll
                for (int r = 0; r < 4; ++r) { buf[r][0] = nbuf[r][0]; buf[r][1] = nbuf[r][1]; }
            }

            // epilogue1 (this half): bias + relu + fp16 pack -> H fragments
            #pragma unroll
            for (int c = 0; c < 2; ++c) {
                #pragma unroll
                for (int k2 = 0; k2 < 4; ++k2) {
                    int nb0 = 2 * k2, nb1 = nb0 + 1;
                    int g0 = hf * 8 + nb0, g1 = hf * 8 + nb1;
                    float bb00 = b1s[g0 * 8 + c0], bb01 = b1s[g0 * 8 + c0 + 1];
                    float bb10 = b1s[g1 * 8 + c0], bb11 = b1s[g1 * 8 + c0 + 1];
                    uint32_t* hd = hh[c][hf * 4 + k2];
                    hd[0] = packh(fmaxf(acc1[c][nb0][0] + bb00, 0.f),
                                  fmaxf(acc1[c][nb0][1] + bb01, 0.f));
                    hd[1] = packh(fmaxf(acc1[c][nb0][2] + bb00, 0.f),
                                  fmaxf(acc1[c][nb0][3] + bb01, 0.f));
                    hd[2] = packh(fmaxf(acc1[c][nb1][0] + bb10, 0.f),
                                  fmaxf(acc1[c][nb1][1] + bb11, 0.f));
                    hd[3] = packh(fmaxf(acc1[c][nb1][2] + bb10, 0.f),
                                  fmaxf(acc1[c][nb1][3] + bb11, 0.f));
                }
            }
        }

        // ---- seg ids + reduction masks (computed late: out of GEMM live range) ----
        int sg[2][2]; bool mk[2][2][3]; bool ld[2][2];
        #pragma unroll
        for (int c = 0; c < 2; ++c) {
            #pragma unroll
            for (int g = 0; g < 2; ++g) {
                int r = 2 * c + g;
                int s = ok[r] ? g_seg_arr[gr[r]] : -1;
                sg[c][g] = s;
                #pragma unroll
                for (int d = 0; d < 3; ++d) {
                    int t = __shfl_down_sync(FM, s, 4 << d);
                    mk[c][g][d] = (rq + (1 << d) < 8) && (t == s);
                }
                int pu = __shfl_up_sync(FM, s, 4);
                ld[c][g] = (rq == 0) || (pu != s);
            }
        }

        // ---- GEMM2 (K=128) in two N-halves + fused epilogue2 ----
        #pragma unroll
        for (int nh = 0; nh < 2; ++nh) {
            float acc2[2][8][4];
            #pragma unroll
            for (int c = 0; c < 2; ++c)
                #pragma unroll
                for (int nb = 0; nb < 8; ++nb)
                    #pragma unroll
                    for (int j = 0; j < 4; ++j) acc2[c][nb][j] = 0.f;

            #pragma unroll
            for (int kb2 = 0; kb2 < 8; ++kb2) {
                const uint2* w = W2F + kb2 * 512 + nh * 256 + lane;
                #pragma unroll
                for (int nbl = 0; nbl < 8; ++nbl) {
                    uint2 b = w[nbl * 32];
                    mma_f16(acc2[0][nbl], hh[0][kb2], b.x, b.y);
                    mma_f16(acc2[1][nbl], hh[1][kb2], b.x, b.y);
                }
            }

            // bias + segmented shfl-reduce + atomics
            #pragma unroll
            for (int c = 0; c < 2; ++c) {
                #pragma unroll
                for (int nbl = 0; nbl < 8; ++nbl) {
                    int nb = nh * 8 + nbl;
                    float bb0 = b2s[nb * 8 + c0], bb1 = b2s[nb * 8 + c0 + 1];
                    float v0 = acc2[c][nbl][0] + bb0;
                    float v1 = acc2[c][nbl][1] + bb1;
                    float v2 = acc2[c][nbl][2] + bb0;
                    float v3 = acc2[c][nbl][3] + bb1;
                    #pragma unroll
                    for (int d = 0; d < 3; ++d) {
                        int dd = 4 << d;
                        float t;
                        t = __shfl_down_sync(FM, v0, dd); if (mk[c][0][d]) v0 += t;
                        t = __shfl_down_sync(FM, v1, dd); if (mk[c][0][d]) v1 += t;
                        t = __shfl_down_sync(FM, v2, dd); if (mk[c][1][d]) v2 += t;
                        t = __shfl_down_sync(FM, v3, dd); if (mk[c][1][d]) v3 += t;
                    }
                    if (ld[c][0] && sg[c][0] >= 0) {
                        float* o = out + (size_t)sg[c][0] * 128 + nb * 8 + c0;
                        atomicAdd(o,     v0);
                        atomicAdd(o + 1, v1);
                    }
                    if (ld[c][1] && sg[c][1] >= 0) {
                        float* o = out + (size_t)sg[c][1] * 128 + nb * 8 + c0;
                        atomicAdd(o,     v2);
                        atomicAdd(o + 1, v3);
                    }
                }
            }
        }
    }
}

// ---------------- launch ----------------
extern "C" void kernel_launch(void* const* d_in, const int* in_sizes, int n_in,
                              void* d_out, int out_size) {
    const float* x  = (const float*)d_in[0];
    const float* hn = (const float*)d_in[1];
    const void*  pt = d_in[2];
    const float* W1 = (const float*)d_in[3];
    const float* b1 = (const float*)d_in[4];
    const float* W2 = (const float*)d_in[5];
    const float* b2 = (const float*)d_in[6];
    float* out = (float*)d_out;

    int N    = in_sizes[0] / 16;
    int Bseg = in_sizes[2] - 1;

    int out4 = out_size / 4;
    int prep_n = (out4 > N) ? out4 : N;
    prep_kernel<<<(prep_n + 255) / 256, 256>>>(pt, (float4*)out, out4, Bseg, N);

    cudaFuncSetAttribute(fused_mma, cudaFuncAttributeMaxDynamicSharedMemorySize, SMEM_BYTES);
    int sms = 0;
    cudaDeviceGetAttribute(&sms, cudaDevAttrMultiProcessorCount, 0);
    if (sms <= 0) sms = 148;
    int nIters = (N + 31) >> 5;
    int warpsPerCta = THREADS / 32;
    int maxCtas = (nIters + warpsPerCta - 1) / warpsPerCta;
    int grid = 3 * sms;
    if (grid > maxCtas) grid = maxCtas;
    fused_mma<<<grid, THREADS, SMEM_BYTES>>>(x, hn, W1, b1, W2, b2, out, N);
}

// round 6
// speedup vs baseline: 4.9667x; 1.1080x over previous
#include <cuda_runtime.h>
#include <cuda_fp16.h>
#include <cstdint>

#define THREADS 128

// smem layout (bytes)
#define W1F_OFF 0          // [9 kb][16 nb][32 lane] uint2 (b0h,b1h) fp16x2
#define W2F_OFF 36864      // [8][16][32] uint2
#define B1_OFF  69632
#define B2_OFF  70144
#define A_OFF   70656      // 4 warp tiles of 32 rows x 152 fp16 (304B pitch)
#define A_PITCH_B 304
#define WARP_TILE_B (32 * A_PITCH_B)   // 9728
#define SMEM_BYTES (A_OFF + 4 * WARP_TILE_B)   // 109568

__device__ int g_seg_arr[2000256];

__device__ __forceinline__ uint32_t packh(float a0, float a1) {
    uint32_t r;
    asm("cvt.rn.f16x2.f32 %0, %1, %2;" : "=r"(r) : "f"(a1), "f"(a0));
    return r;
}
__device__ __forceinline__ void mma_f16(float* c, const uint32_t* a, uint32_t b0, uint32_t b1) {
    asm volatile("mma.sync.aligned.m16n8k16.row.col.f32.f16.f16.f32 "
                 "{%0,%1,%2,%3}, {%4,%5,%6,%7}, {%8,%9}, {%0,%1,%2,%3};"
                 : "+f"(c[0]), "+f"(c[1]), "+f"(c[2]), "+f"(c[3])
                 : "r"(a[0]), "r"(a[1]), "r"(a[2]), "r"(a[3]), "r"(b0), "r"(b1));
}
__device__ __forceinline__ void ldmx4(uint32_t* a, uint32_t saddr) {
    asm volatile("ldmatrix.sync.aligned.m8n8.x4.shared.b16 {%0,%1,%2,%3}, [%4];"
                 : "=r"(a[0]), "=r"(a[1]), "=r"(a[2]), "=r"(a[3]) : "r"(saddr));
}
__device__ __forceinline__ void sts64(uint32_t sa, uint32_t p0, uint32_t p1) {
    asm volatile("st.shared.v2.u32 [%0], {%1, %2};" :: "r"(sa), "r"(p0), "r"(p1));
}

// ---------------- prep: zero output + seg ids ----------------
__global__ void prep_kernel(const void* __restrict__ ptr_raw, float4* __restrict__ out4,
                            int out4_elems, int Bseg, int N) {
    int idx = blockIdx.x * blockDim.x + threadIdx.x;
    if (idx < out4_elems) out4[idx] = make_float4(0.f, 0.f, 0.f, 0.f);
    if (idx < N) {
        const int* p32 = (const int*)ptr_raw;
        const long long* p64 = (const long long*)ptr_raw;
        bool is64 = (p32[Bseg] != N);
        int lo = 0, hi = Bseg + 1;
        while (lo < hi) {
            int mid = (lo + hi) >> 1;
            long long v = is64 ? p64[mid] : (long long)p32[mid];
            if (v <= (long long)idx) lo = mid + 1; else hi = mid;
        }
        g_seg_arr[idx] = lo - 1;
    }
}

// ---------------- fused MLP + segment-sum: fp16, smem-staged A + ldmatrix ----------------
__global__ __launch_bounds__(THREADS, 2)
void fused_mma(const float* __restrict__ x, const float* __restrict__ hn,
               const float* __restrict__ W1g, const float* __restrict__ b1g,
               const float* __restrict__ W2g, const float* __restrict__ b2g,
               float* __restrict__ out, int N) {
    extern __shared__ char smc[];
    uint2* W1F = (uint2*)(smc + W1F_OFF);
    uint2* W2F = (uint2*)(smc + W2F_OFF);
    float* b1s = (float*)(smc + B1_OFF);
    float* b2s = (float*)(smc + B2_OFF);

    const int tid  = threadIdx.x;
    const int lane = tid & 31;
    const int wid  = tid >> 5;

    // ---- build fp16 B-fragment images in smem (once per CTA) ----
    for (int s = tid; s < 9 * 16 * 32; s += THREADS) {
        int kb = s >> 9, nb = (s >> 5) & 15, ln = s & 31;
        int k0 = kb * 16 + 2 * (ln & 3);
        int n  = nb * 8 + (ln >> 2);
        uint32_t b0 = packh(W1g[k0 * 128 + n],       W1g[(k0 + 1) * 128 + n]);
        uint32_t b1 = packh(W1g[(k0 + 8) * 128 + n], W1g[(k0 + 9) * 128 + n]);
        W1F[s] = make_uint2(b0, b1);
    }
    for (int s = tid; s < 8 * 16 * 32; s += THREADS) {
        int kb = s >> 9, nb = (s >> 5) & 15, ln = s & 31;
        int k0 = kb * 16 + 2 * (ln & 3);
        int n  = nb * 8 + (ln >> 2);
        uint32_t b0 = packh(W2g[k0 * 128 + n],       W2g[(k0 + 1) * 128 + n]);
        uint32_t b1 = packh(W2g[(k0 + 8) * 128 + n], W2g[(k0 + 9) * 128 + n]);
        W2F[s] = make_uint2(b0, b1);
    }
    if (tid < 128) { b1s[tid] = b1g[tid]; b2s[tid] = b2g[tid]; }
    __syncthreads();

    uint32_t smem_u32;
    asm("{ .reg .u64 t; cvta.to.shared.u64 t, %1; cvt.u32.u64 %0, t; }"
        : "=r"(smem_u32) : "l"(smc));
    const uint32_t tile = smem_u32 + A_OFF + wid * WARP_TILE_B;

    const int rq = lane >> 2;           // row within 8-row group
    const int c0 = 2 * (lane & 3);      // col pair within 8-col n-block
    const int totalWarps = gridDim.x * (THREADS / 32);
    const int wgid = blockIdx.x * (THREADS / 32) + wid;
    const int nIters = (N + 31) >> 5;
    const unsigned FM = 0xffffffffu;

    // ldmatrix lane addressing (within a 16x16 fragment tile)
    const int lm_row = lane & 15;            // rows 0..15
    const int lm_col = (lane >> 4) * 8;      // fp16 col 0 or 8

    // ---- stage tile for iteration 'it' into this warp's smem tile ----
    auto stage = [&](int it) {
        if (it >= nIters) return;
        const int base = it << 5;
        const float4 z4 = make_float4(0.f, 0.f, 0.f, 0.f);
        // x part: 4 insts, 8 rows each (lane/4 = row-in-group, lane%4 = float4 col)
        #pragma unroll
        for (int i = 0; i < 4; ++i) {
            int r = i * 8 + (lane >> 2);
            int g = base + r;
            float4 v = (g < N) ? *(const float4*)(x + (size_t)g * 16 + (lane & 3) * 4) : z4;
            sts64(tile + r * A_PITCH_B + (lane & 3) * 8,
                  packh(v.x, v.y), packh(v.z, v.w));
        }
        // hn part: 32 insts, one row each (lane = float4 col)
        #pragma unroll 8
        for (int r = 0; r < 32; ++r) {
            int g = base + r;
            float4 v = (g < N) ? *(const float4*)(hn + (size_t)g * 128 + lane * 4) : z4;
            sts64(tile + r * A_PITCH_B + 32 + lane * 8,
                  packh(v.x, v.y), packh(v.z, v.w));
        }
    };

    stage(wgid);

    for (int it = wgid; it < nIters; it += totalWarps) {
        const int base = it << 5;
        __syncwarp();

        // ---- GEMM1: K=144, A from smem via ldmatrix, single pass ----
        float acc1[2][16][4];
        #pragma unroll
        for (int c = 0; c < 2; ++c)
            #pragma unroll
            for (int nb = 0; nb < 16; ++nb)
                #pragma unroll
                for (int j = 0; j < 4; ++j) acc1[c][nb][j] = 0.f;

        #pragma unroll
        for (int kb = 0; kb < 9; ++kb) {
            uint32_t a[2][4];
            #pragma unroll
            for (int c = 0; c < 2; ++c)
                ldmx4(a[c], tile + (c * 16 + lm_row) * A_PITCH_B + (kb * 16 + lm_col) * 2);
            const uint2* w = W1F + kb * 512 + lane;
            #pragma unroll
            for (int nb = 0; nb < 16; ++nb) {
                uint2 b = w[nb * 32];
                mma_f16(acc1[0][nb], a[0], b.x, b.y);
                mma_f16(acc1[1][nb], a[1], b.x, b.y);
            }
        }

        // ---- epilogue1: bias + relu + fp16 pack -> H fragments ----
        uint32_t hh[2][8][4];
        #pragma unroll
        for (int c = 0; c < 2; ++c) {
            #pragma unroll
            for (int k2 = 0; k2 < 8; ++k2) {
                int nb0 = 2 * k2, nb1 = nb0 + 1;
                float bb00 = b1s[nb0 * 8 + c0], bb01 = b1s[nb0 * 8 + c0 + 1];
                float bb10 = b1s[nb1 * 8 + c0], bb11 = b1s[nb1 * 8 + c0 + 1];
                hh[c][k2][0] = packh(fmaxf(acc1[c][nb0][0] + bb00, 0.f),
                                     fmaxf(acc1[c][nb0][1] + bb01, 0.f));
                hh[c][k2][1] = packh(fmaxf(acc1[c][nb0][2] + bb00, 0.f),
                                     fmaxf(acc1[c][nb0][3] + bb01, 0.f));
                hh[c][k2][2] = packh(fmaxf(acc1[c][nb1][0] + bb10, 0.f),
                                     fmaxf(acc1[c][nb1][1] + bb11, 0.f));
                hh[c][k2][3] = packh(fmaxf(acc1[c][nb1][2] + bb10, 0.f),
                                     fmaxf(acc1[c][nb1][3] + bb11, 0.f));
            }
        }

        // A tile fully consumed; stage next iteration (LDG hides under GEMM2)
        __syncwarp();
        stage(it + totalWarps);

        // ---- seg ids + reduction masks ----
        int gr[4];
        #pragma unroll
        for (int r = 0; r < 4; ++r) gr[r] = base + r * 8 + rq;
        int sg[2][2]; bool mk[2][2][3]; bool ld[2][2];
        #pragma unroll
        for (int c = 0; c < 2; ++c) {
            #pragma unroll
            for (int g = 0; g < 2; ++g) {
                int r = 2 * c + g;
                int s = (gr[r] < N) ? g_seg_arr[gr[r]] : -1;
                sg[c][g] = s;
                #pragma unroll
                for (int d = 0; d < 3; ++d) {
                    int t = __shfl_down_sync(FM, s, 4 << d);
                    mk[c][g][d] = (rq + (1 << d) < 8) && (t == s);
                }
                int pu = __shfl_up_sync(FM, s, 4);
                ld[c][g] = (rq == 0) || (pu != s);
            }
        }

        // ---- GEMM2 (K=128) in two N-halves + fused epilogue2 ----
        #pragma unroll
        for (int nh = 0; nh < 2; ++nh) {
            float acc2[2][8][4];
            #pragma unroll
            for (int c = 0; c < 2; ++c)
                #pragma unroll
                for (int nb = 0; nb < 8; ++nb)
                    #pragma unroll
                    for (int j = 0; j < 4; ++j) acc2[c][nb][j] = 0.f;

            #pragma unroll
            for (int kb2 = 0; kb2 < 8; ++kb2) {
                const uint2* w = W2F + kb2 * 512 + nh * 256 + lane;
                #pragma unroll
                for (int nbl = 0; nbl < 8; ++nbl) {
                    uint2 b = w[nbl * 32];
                    mma_f16(acc2[0][nbl], hh[0][kb2], b.x, b.y);
                    mma_f16(acc2[1][nbl], hh[1][kb2], b.x, b.y);
                }
            }

            #pragma unroll
            for (int c = 0; c < 2; ++c) {
                #pragma unroll
                for (int nbl = 0; nbl < 8; ++nbl) {
                    int nb = nh * 8 + nbl;
                    float bb0 = b2s[nb * 8 + c0], bb1 = b2s[nb * 8 + c0 + 1];
                    float v0 = acc2[c][nbl][0] + bb0;
                    float v1 = acc2[c][nbl][1] + bb1;
                    float v2 = acc2[c][nbl][2] + bb0;
                    float v3 = acc2[c][nbl][3] + bb1;
                    #pragma unroll
                    for (int d = 0; d < 3; ++d) {
                        int dd = 4 << d;
                        float t;
                        t = __shfl_down_sync(FM, v0, dd); if (mk[c][0][d]) v0 += t;
                        t = __shfl_down_sync(FM, v1, dd); if (mk[c][0][d]) v1 += t;
                        t = __shfl_down_sync(FM, v2, dd); if (mk[c][1][d]) v2 += t;
                        t = __shfl_down_sync(FM, v3, dd); if (mk[c][1][d]) v3 += t;
                    }
                    if (ld[c][0] && sg[c][0] >= 0) {
                        float* o = out + (size_t)sg[c][0] * 128 + nb * 8 + c0;
                        atomicAdd(o,     v0);
                        atomicAdd(o + 1, v1);
                    }
                    if (ld[c][1] && sg[c][1] >= 0) {
                        float* o = out + (size_t)sg[c][1] * 128 + nb * 8 + c0;
                        atomicAdd(o,     v2);
                        atomicAdd(o + 1, v3);
                    }
                }
            }
        }
    }
}

// ---------------- launch ----------------
extern "C" void kernel_launch(void* const* d_in, const int* in_sizes, int n_in,
                              void* d_out, int out_size) {
    const float* x  = (const float*)d_in[0];
    const float* hn = (const float*)d_in[1];
    const void*  pt = d_in[2];
    const float* W1 = (const float*)d_in[3];
    const float* b1 = (const float*)d_in[4];
    const float* W2 = (const float*)d_in[5];
    const float* b2 = (const float*)d_in[6];
    float* out = (float*)d_out;

    int N    = in_sizes[0] / 16;
    int Bseg = in_sizes[2] - 1;

    int out4 = out_size / 4;
    int prep_n = (out4 > N) ? out4 : N;
    prep_kernel<<<(prep_n + 255) / 256, 256>>>(pt, (float4*)out, out4, Bseg, N);

    cudaFuncSetAttribute(fused_mma, cudaFuncAttributeMaxDynamicSharedMemorySize, SMEM_BYTES);
    int sms = 0;
    cudaDeviceGetAttribute(&sms, cudaDevAttrMultiProcessorCount, 0);
    if (sms <= 0) sms = 148;
    int nIters = (N + 31) >> 5;
    int warpsPerCta = THREADS / 32;
    int maxCtas = (nIters + warpsPerCta - 1) / warpsPerCta;
    int grid = 2 * sms;
    if (grid > maxCtas) grid = maxCtas;
    fused_mma<<<grid, THREADS, SMEM_BYTES>>>(x, hn, W1, b1, W2, b2, out, N);
}

// round 7
// speedup vs baseline: 5.1849x; 1.0439x over previous
#include <cuda_runtime.h>
#include <cuda_fp16.h>
#include <cstdint>

#define THREADS 384
#define NWARPS  12

// smem layout (bytes)
#define W1F_OFF 0          // [9 kb][16 nb][32 lane] uint2 (b0h,b1h) fp16x2
#define W2F_OFF 36864      // [8][16][32] uint2
#define B1_OFF  69632
#define B2_OFF  70144
#define A_OFF   70656      // NWARPS warp tiles of 32 rows x 152 fp16 (304B pitch)
#define A_PITCH_B 304
#define WARP_TILE_B (32 * A_PITCH_B)                  // 9728
#define SMEM_BYTES (A_OFF + NWARPS * WARP_TILE_B)     // 187392

__device__ int g_seg_arr[2000256];

__device__ __forceinline__ uint32_t packh(float a0, float a1) {
    uint32_t r;
    asm("cvt.rn.f16x2.f32 %0, %1, %2;" : "=r"(r) : "f"(a1), "f"(a0));
    return r;
}
__device__ __forceinline__ void mma_f16(float* c, const uint32_t* a, uint32_t b0, uint32_t b1) {
    asm volatile("mma.sync.aligned.m16n8k16.row.col.f32.f16.f16.f32 "
                 "{%0,%1,%2,%3}, {%4,%5,%6,%7}, {%8,%9}, {%0,%1,%2,%3};"
                 : "+f"(c[0]), "+f"(c[1]), "+f"(c[2]), "+f"(c[3])
                 : "r"(a[0]), "r"(a[1]), "r"(a[2]), "r"(a[3]), "r"(b0), "r"(b1));
}
__device__ __forceinline__ void ldmx4(uint32_t* a, uint32_t saddr) {
    asm volatile("ldmatrix.sync.aligned.m8n8.x4.shared.b16 {%0,%1,%2,%3}, [%4];"
                 : "=r"(a[0]), "=r"(a[1]), "=r"(a[2]), "=r"(a[3]) : "r"(saddr));
}
__device__ __forceinline__ void sts64(uint32_t sa, uint32_t p0, uint32_t p1) {
    asm volatile("st.shared.v2.u32 [%0], {%1, %2};" :: "r"(sa), "r"(p0), "r"(p1));
}

// ---------------- prep: zero output + seg ids ----------------
__global__ void prep_kernel(const void* __restrict__ ptr_raw, float4* __restrict__ out4,
                            int out4_elems, int Bseg, int N) {
    int idx = blockIdx.x * blockDim.x + threadIdx.x;
    if (idx < out4_elems) out4[idx] = make_float4(0.f, 0.f, 0.f, 0.f);
    if (idx < N) {
        const int* p32 = (const int*)ptr_raw;
        const long long* p64 = (const long long*)ptr_raw;
        bool is64 = (p32[Bseg] != N);
        int lo = 0, hi = Bseg + 1;
        while (lo < hi) {
            int mid = (lo + hi) >> 1;
            long long v = is64 ? p64[mid] : (long long)p32[mid];
            if (v <= (long long)idx) lo = mid + 1; else hi = mid;
        }
        g_seg_arr[idx] = lo - 1;
    }
}

// ---------------- fused MLP + segment-sum ----------------
__global__ __launch_bounds__(THREADS, 1)
void fused_mma(const float* __restrict__ x, const float* __restrict__ hn,
               const float* __restrict__ W1g, const float* __restrict__ b1g,
               const float* __restrict__ W2g, const float* __restrict__ b2g,
               float* __restrict__ out, int N) {
    extern __shared__ char smc[];
    uint2* W1F = (uint2*)(smc + W1F_OFF);
    uint2* W2F = (uint2*)(smc + W2F_OFF);
    float* b1s = (float*)(smc + B1_OFF);
    float* b2s = (float*)(smc + B2_OFF);

    const int tid  = threadIdx.x;
    const int lane = tid & 31;
    const int wid  = tid >> 5;

    // ---- build fp16 B-fragment images in smem (once per CTA) ----
    for (int s = tid; s < 9 * 16 * 32; s += THREADS) {
        int kb = s >> 9, nb = (s >> 5) & 15, ln = s & 31;
        int k0 = kb * 16 + 2 * (ln & 3);
        int n  = nb * 8 + (ln >> 2);
        uint32_t b0 = packh(W1g[k0 * 128 + n],       W1g[(k0 + 1) * 128 + n]);
        uint32_t b1 = packh(W1g[(k0 + 8) * 128 + n], W1g[(k0 + 9) * 128 + n]);
        W1F[s] = make_uint2(b0, b1);
    }
    for (int s = tid; s < 8 * 16 * 32; s += THREADS) {
        int kb = s >> 9, nb = (s >> 5) & 15, ln = s & 31;
        int k0 = kb * 16 + 2 * (ln & 3);
        int n  = nb * 8 + (ln >> 2);
        uint32_t b0 = packh(W2g[k0 * 128 + n],       W2g[(k0 + 1) * 128 + n]);
        uint32_t b1 = packh(W2g[(k0 + 8) * 128 + n], W2g[(k0 + 9) * 128 + n]);
        W2F[s] = make_uint2(b0, b1);
    }
    if (tid < 128) { b1s[tid] = b1g[tid]; b2s[tid] = b2g[tid]; }
    __syncthreads();

    uint32_t smem_u32;
    asm("{ .reg .u64 t; cvta.to.shared.u64 t, %1; cvt.u32.u64 %0, t; }"
        : "=r"(smem_u32) : "l"(smc));
    const uint32_t tile = smem_u32 + A_OFF + wid * WARP_TILE_B;

    const int rq = lane >> 2;           // row within 8-row group
    const int c0 = 2 * (lane & 3);      // col pair within 8-col n-block
    const int totalWarps = gridDim.x * NWARPS;
    const int wgid = blockIdx.x * NWARPS + wid;
    const int nIters = (N + 31) >> 5;
    const unsigned FM = 0xffffffffu;

    const int lm_row = lane & 15;
    const int lm_col = (lane >> 4) * 8;

    auto stage = [&](int it) {
        if (it >= nIters) return;
        const int base = it << 5;
        const float4 z4 = make_float4(0.f, 0.f, 0.f, 0.f);
        #pragma unroll
        for (int i = 0; i < 4; ++i) {
            int r = i * 8 + (lane >> 2);
            int g = base + r;
            float4 v = (g < N) ? *(const float4*)(x + (size_t)g * 16 + (lane & 3) * 4) : z4;
            sts64(tile + r * A_PITCH_B + (lane & 3) * 8,
                  packh(v.x, v.y), packh(v.z, v.w));
        }
        #pragma unroll 8
        for (int r = 0; r < 32; ++r) {
            int g = base + r;
            float4 v = (g < N) ? *(const float4*)(hn + (size_t)g * 128 + lane * 4) : z4;
            sts64(tile + r * A_PITCH_B + 32 + lane * 8,
                  packh(v.x, v.y), packh(v.z, v.w));
        }
    };

    stage(wgid);

    for (int it = wgid; it < nIters; it += totalWarps) {
        const int base = it << 5;
        __syncwarp();

        uint32_t hh[2][8][4];   // H fragments, filled across the two GEMM1 passes

        // ---- GEMM1: K=144, two N-half passes (A re-read via cheap ldmatrix) ----
        #pragma unroll
        for (int hf = 0; hf < 2; ++hf) {
            float acc1[2][8][4];
            #pragma unroll
            for (int c = 0; c < 2; ++c)
                #pragma unroll
                for (int nb = 0; nb < 8; ++nb)
                    #pragma unroll
                    for (int j = 0; j < 4; ++j) acc1[c][nb][j] = 0.f;

            #pragma unroll
            for (int kb = 0; kb < 9; ++kb) {
                uint32_t a[2][4];
                #pragma unroll
                for (int c = 0; c < 2; ++c)
                    ldmx4(a[c], tile + (c * 16 + lm_row) * A_PITCH_B + (kb * 16 + lm_col) * 2);
                const uint2* w = W1F + kb * 512 + hf * 256 + lane;
                #pragma unroll
                for (int nbl = 0; nbl < 8; ++nbl) {
                    uint2 b = w[nbl * 32];
                    mma_f16(acc1[0][nbl], a[0], b.x, b.y);
                    mma_f16(acc1[1][nbl], a[1], b.x, b.y);
                }
            }

            // epilogue1 (this half): bias + relu + fp16 pack -> H fragments
            #pragma unroll
            for (int c = 0; c < 2; ++c) {
                #pragma unroll
                for (int k2 = 0; k2 < 4; ++k2) {
                    int nb0 = 2 * k2, nb1 = nb0 + 1;
                    int g0 = hf * 8 + nb0, g1 = hf * 8 + nb1;
                    float bb00 = b1s[g0 * 8 + c0], bb01 = b1s[g0 * 8 + c0 + 1];
                    float bb10 = b1s[g1 * 8 + c0], bb11 = b1s[g1 * 8 + c0 + 1];
                    uint32_t* hd = hh[c][hf * 4 + k2];
                    hd[0] = packh(fmaxf(acc1[c][nb0][0] + bb00, 0.f),
                                  fmaxf(acc1[c][nb0][1] + bb01, 0.f));
                    hd[1] = packh(fmaxf(acc1[c][nb0][2] + bb00, 0.f),
                                  fmaxf(acc1[c][nb0][3] + bb01, 0.f));
                    hd[2] = packh(fmaxf(acc1[c][nb1][0] + bb10, 0.f),
                                  fmaxf(acc1[c][nb1][1] + bb11, 0.f));
                    hd[3] = packh(fmaxf(acc1[c][nb1][2] + bb10, 0.f),
                                  fmaxf(acc1[c][nb1][3] + bb11, 0.f));
                }
            }
        }

        // A tile consumed; stage next iteration (LDG hides under GEMM2)
        __syncwarp();
        stage(it + totalWarps);

        // ---- seg ids + reduction masks ----
        int gr[4];
        #pragma unroll
        for (int r = 0; r < 4; ++r) gr[r] = base + r * 8 + rq;
        int sg[2][2]; bool mk[2][2][3]; bool ld[2][2];
        #pragma unroll
        for (int c = 0; c < 2; ++c) {
            #pragma unroll
            for (int g = 0; g < 2; ++g) {
                int r = 2 * c + g;
                int s = (gr[r] < N) ? g_seg_arr[gr[r]] : -1;
                sg[c][g] = s;
                #pragma unroll
                for (int d = 0; d < 3; ++d) {
                    int t = __shfl_down_sync(FM, s, 4 << d);
                    mk[c][g][d] = (rq + (1 << d) < 8) && (t == s);
                }
                int pu = __shfl_up_sync(FM, s, 4);
                ld[c][g] = (rq == 0) || (pu != s);
            }
        }

        // ---- GEMM2 (K=128) in two N-halves + fused epilogue2 ----
        #pragma unroll
        for (int nh = 0; nh < 2; ++nh) {
            float acc2[2][8][4];
            #pragma unroll
            for (int c = 0; c < 2; ++c)
                #pragma unroll
                for (int nb = 0; nb < 8; ++nb)
                    #pragma unroll
                    for (int j = 0; j < 4; ++j) acc2[c][nb][j] = 0.f;

            #pragma unroll
            for (int kb2 = 0; kb2 < 8; ++kb2) {
                const uint2* w = W2F + kb2 * 512 + nh * 256 + lane;
                #pragma unroll
                for (int nbl = 0; nbl < 8; ++nbl) {
                    uint2 b = w[nbl * 32];
                    mma_f16(acc2[0][nbl], hh[0][kb2], b.x, b.y);
                    mma_f16(acc2[1][nbl], hh[1][kb2], b.x, b.y);
                }
            }

            #pragma unroll
            for (int c = 0; c < 2; ++c) {
                #pragma unroll
                for (int nbl = 0; nbl < 8; ++nbl) {
                    int nb = nh * 8 + nbl;
                    float bb0 = b2s[nb * 8 + c0], bb1 = b2s[nb * 8 + c0 + 1];
                    float v0 = acc2[c][nbl][0] + bb0;
                    float v1 = acc2[c][nbl][1] + bb1;
                    float v2 = acc2[c][nbl][2] + bb0;
                    float v3 = acc2[c][nbl][3] + bb1;
                    #pragma unroll
                    for (int d = 0; d < 3; ++d) {
                        int dd = 4 << d;
                        float t;
                        t = __shfl_down_sync(FM, v0, dd); if (mk[c][0][d]) v0 += t;
                        t = __shfl_down_sync(FM, v1, dd); if (mk[c][0][d]) v1 += t;
                        t = __shfl_down_sync(FM, v2, dd); if (mk[c][1][d]) v2 += t;
                        t = __shfl_down_sync(FM, v3, dd); if (mk[c][1][d]) v3 += t;
                    }
                    if (ld[c][0] && sg[c][0] >= 0) {
                        float* o = out + (size_t)sg[c][0] * 128 + nb * 8 + c0;
                        atomicAdd(o,     v0);
                        atomicAdd(o + 1, v1);
                    }
                    if (ld[c][1] && sg[c][1] >= 0) {
                        float* o = out + (size_t)sg[c][1] * 128 + nb * 8 + c0;
                        atomicAdd(o,     v2);
                        atomicAdd(o + 1, v3);
                    }
                }
            }
        }
    }
}

// ---------------- launch ----------------
extern "C" void kernel_launch(void* const* d_in, const int* in_sizes, int n_in,
                              void* d_out, int out_size) {
    const float* x  = (const float*)d_in[0];
    const float* hn = (const float*)d_in[1];
    const void*  pt = d_in[2];
    const float* W1 = (const float*)d_in[3];
    const float* b1 = (const float*)d_in[4];
    const float* W2 = (const float*)d_in[5];
    const float* b2 = (const float*)d_in[6];
    float* out = (float*)d_out;

    int N    = in_sizes[0] / 16;
    int Bseg = in_sizes[2] - 1;

    int out4 = out_size / 4;
    int prep_n = (out4 > N) ? out4 : N;
    prep_kernel<<<(prep_n + 255) / 256, 256>>>(pt, (float4*)out, out4, Bseg, N);

    cudaFuncSetAttribute(fused_mma, cudaFuncAttributeMaxDynamicSharedMemorySize, SMEM_BYTES);
    int sms = 0;
    cudaDeviceGetAttribute(&sms, cudaDevAttrMultiProcessorCount, 0);
    if (sms <= 0) sms = 148;
    int nIters = (N + 31) >> 5;
    int maxCtas = (nIters + NWARPS - 1) / NWARPS;
    int grid = (sms < maxCtas) ? sms : maxCtas;
    fused_mma<<<grid, THREADS, SMEM_BYTES>>>(x, hn, W1, b1, W2, b2, out, N);
}